// round 14
// baseline (speedup 1.0000x reference)
#include <cuda_runtime.h>
#include <math.h>
#include <stdint.h>

// ---------------------------------------------------------------------------
// Problem constants
// ---------------------------------------------------------------------------
#define BN 2
#define TN 1024
#define CN 768
#define HN 12
#define HDN 64
#define LN 4
#define DIN 64
#define VN 50304
#define CFN 3072          // 4*C
#define MN (BN*TN)        // 2048 rows
#define NAQ 2432          // 3*C + 128 (fused qkv + qint|kint)

// ---------------------------------------------------------------------------
// Scratch (static device globals; allocation APIs are forbidden)
// ---------------------------------------------------------------------------
__device__ float g_x[MN*CN];
__device__ float g_qkv[MN*3*CN];
__device__ float g_p[BN*TN*TN];     // log-p, layout [b][k][q]
__device__ float g_mask[BN*TN*TN];  // accumulated attn_mask, layout [b][q][k]

// bf16 hi/lo activation planes
__device__ __align__(16) uint16_t g_h_hi[MN*CN],  g_h_lo[MN*CN];
__device__ __align__(16) uint16_t g_y_hi[MN*CN],  g_y_lo[MN*CN];
__device__ __align__(16) uint16_t g_qk_hi[MN*128], g_qk_lo[MN*128];
__device__ __align__(16) uint16_t g_fc_hi[MN*CFN], g_fc_lo[MN*CFN];

// bf16 hi/lo weight planes (split once per launch)
__device__ __align__(16) uint16_t g_waq_hi[LN*NAQ*CN], g_waq_lo[LN*NAQ*CN];
__device__ __align__(16) uint16_t g_wpj_hi[LN*CN*CN],   g_wpj_lo[LN*CN*CN];
__device__ __align__(16) uint16_t g_wfc_hi[LN*CFN*CN],  g_wfc_lo[LN*CFN*CN];
__device__ __align__(16) uint16_t g_wf2_hi[LN*CN*CFN],  g_wf2_lo[LN*CN*CFN];
__device__ __align__(16) uint16_t g_wte_hi[(size_t)VN*CN], g_wte_lo[(size_t)VN*CN];

// ---------------------------------------------------------------------------
// bf16 split helpers
// ---------------------------------------------------------------------------
__device__ __forceinline__ void pack2(float a, float b, uint32_t& h, uint32_t& l) {
    asm("cvt.rn.bf16x2.f32 %0, %1, %2;" : "=r"(h) : "f"(b), "f"(a));
    float ra = a - __uint_as_float(h << 16);
    float rb = b - __uint_as_float(h & 0xFFFF0000u);
    asm("cvt.rn.bf16x2.f32 %0, %1, %2;" : "=r"(l) : "f"(rb), "f"(ra));
}

__device__ __forceinline__ void split1(float v, uint16_t* hp, uint16_t* lp) {
    uint16_t h;
    asm("cvt.rn.bf16.f32 %0, %1;" : "=h"(h) : "f"(v));
    float hf = __uint_as_float(((uint32_t)h) << 16);
    uint16_t l;
    asm("cvt.rn.bf16.f32 %0, %1;" : "=h"(l) : "f"(v - hf));
    *hp = h; *lp = l;
}

// split a f32 tensor into hi/lo bf16 planes (n4 = count/4)
__global__ void k_split(const float* __restrict__ src, uint16_t* __restrict__ hi,
                        uint16_t* __restrict__ lo, int n4) {
    int i = blockIdx.x * blockDim.x + threadIdx.x;
    if (i >= n4) return;
    float4 v = ((const float4*)src)[i];
    uint32_t h0, l0, h1, l1;
    pack2(v.x, v.y, h0, l0);
    pack2(v.z, v.w, h1, l1);
    ((uint2*)hi)[i] = make_uint2(h0, h1);
    ((uint2*)lo)[i] = make_uint2(l0, l1);
}

// build fused [L][2432][CN] weight planes: rows 0..2303 attn_w, 2304..2367
// qint_w, 2368..2431 kint_w
__global__ void k_prep(const float* __restrict__ aw, const float* __restrict__ qw,
                       const float* __restrict__ kw,
                       uint16_t* __restrict__ hi, uint16_t* __restrict__ lo) {
    int i = blockIdx.x * blockDim.x + threadIdx.x;   // pair index
    if (i >= LN*NAQ*CN/2) return;
    int e = i*2;
    int c = e % CN;
    int r = (e / CN) % NAQ;
    int l = e / (NAQ*CN);
    const float* srow;
    if (r < 2304)      srow = aw + ((size_t)l*2304 + r)*CN;
    else if (r < 2368) srow = qw + ((size_t)l*64 + (r-2304))*CN;
    else               srow = kw + ((size_t)l*64 + (r-2368))*CN;
    uint32_t h, lo2;
    pack2(srow[c], srow[c+1], h, lo2);
    *(uint32_t*)(hi + e) = h;
    *(uint32_t*)(lo + e) = lo2;
}

// ---------------------------------------------------------------------------
// Embedding: x = wte[idx] + wpe[:T]
// ---------------------------------------------------------------------------
__global__ void k_embed(const float* __restrict__ wte, const float* __restrict__ wpe,
                        const int* __restrict__ idx, float* __restrict__ x) {
    int i = blockIdx.x * blockDim.x + threadIdx.x;
    if (i >= MN*CN) return;
    int c = i % CN;
    int bt = i / CN;
    int t = bt % TN;
    x[i] = wte[(size_t)idx[bt]*CN + c] + wpe[t*CN + c];
}

__global__ void k_zero(float* __restrict__ p, int n) {
    int i = blockIdx.x * blockDim.x + threadIdx.x;
    for (; i < n; i += gridDim.x * blockDim.x) p[i] = 0.0f;
}

// ---------------------------------------------------------------------------
// LayerNorm (block per row), emits bf16 hi/lo planes
// ---------------------------------------------------------------------------
__global__ void k_ln(const float* __restrict__ x, const float* __restrict__ w,
                     const float* __restrict__ b,
                     uint16_t* __restrict__ ohi, uint16_t* __restrict__ olo) {
    int row = blockIdx.x;
    const float* xr = x + (size_t)row*CN;
    __shared__ float red[256];
    int t = threadIdx.x;
    float lx0 = xr[t], lx1 = xr[t+256], lx2 = xr[t+512];
    red[t] = lx0 + lx1 + lx2;
    __syncthreads();
    for (int st = 128; st > 0; st >>= 1) {
        if (t < st) red[t] += red[t+st];
        __syncthreads();
    }
    float mu = red[0] / (float)CN;
    __syncthreads();
    float d0 = lx0-mu, d1 = lx1-mu, d2 = lx2-mu;
    red[t] = d0*d0 + d1*d1 + d2*d2;
    __syncthreads();
    for (int st = 128; st > 0; st >>= 1) {
        if (t < st) red[t] += red[t+st];
        __syncthreads();
    }
    float var = red[0] / (float)CN;
    float inv = 1.0f / sqrtf(var + 1e-5f);
    size_t base = (size_t)row*CN;
    split1(d0*inv*w[t]     + b[t],     ohi + base + t,     olo + base + t);
    split1(d1*inv*w[t+256] + b[t+256], ohi + base + t+256, olo + base + t+256);
    split1(d2*inv*w[t+512] + b[t+512], ohi + base + t+512, olo + base + t+512);
}

// ---------------------------------------------------------------------------
// GELU helper (tanh approximation, matching reference constants)
// ---------------------------------------------------------------------------
__device__ __forceinline__ float gelu1(float v) {
    float inner = 0.7978845608028654f * (v + 0.044715f*v*v*v);
    return 0.5f*v*(1.0f + tanhf(inner));
}

// ---------------------------------------------------------------------------
// entmax (alpha=1.000001), f32-FAITHFUL bisection — replicates the reference's
// f32 base quantization (clip(Xs-tau) rounded to ulp(1), amplified 1e6x in the
// logit). Freezes when tau_lo + dm == tau_lo (~5 iters). Returns log p.
// ---------------------------------------------------------------------------
__device__ __forceinline__ float lg1e6(float b, float& z) {
    float t = b - 1.0f;
    float u = 1.0e6f * t;
    float e = fmaf(1.0e6f, t, -u);
    float c = fmaf(u*t, fmaf(t, fmaf(-0.25f, t, 0.33333333333333333f), -0.5f), e);
    z = u + c;
    return expf(u) * (1.0f + c*(1.0f + 0.5f*c));
}

__device__ __forceinline__ float entmax_ep(float raw, bool gt, float am1f,
                                           float halfpow, float ib) {
    if (!gt) return 0.0f;
    float r   = raw*0.125f + ib;
    float Xs0 = r * am1f;
    float maxv = fmaxf(Xs0, 0.0f);
    float tau_lo = maxv - 1.0f;
    float tau_hi = maxv - halfpow;
    float dm = tau_hi - tau_lo;
    float zt;
    float f_lo = (lg1e6(fmaxf(Xs0 - tau_lo, 0.0f), zt)
                + lg1e6(fmaxf(-tau_lo, 0.0f), zt)) - 1.0f;
    float z0 = 0.0f, z1 = 0.0f;
#pragma unroll 1
    for (int it = 0; it < 50; ++it) {
        dm *= 0.5f;
        float tm = tau_lo + dm;
        float p0 = lg1e6(fmaxf(Xs0 - tm, 0.0f), z0);
        float p1 = lg1e6(fmaxf(-tm, 0.0f), z1);
        float fm = (p0 + p1) - 1.0f;
        bool take = (fm * f_lo >= 0.0f);
        if (tm == tau_lo) break;
        if (take) tau_lo = tm;
    }
    float d = z1 - z0;
    return (d <= 0.0f) ? -log1pf(expf(d)) : -(d + log1pf(expf(-d)));
}

// ---------------------------------------------------------------------------
// 2xBF16 tensor-core GEMM on pre-split hi/lo planes.
// cp.async 3-stage pipeline, ldmatrix, one barrier per BK=16 tile.
// Block tile 128x128, 8 warps (4Mx2N), warp tile 32x64.
// mode: 0 plain, 1 gelu, 2 fused-qkv split epilogue (n<2304 -> f32 qkv,
//       n>=2304 -> qk planes stride 128), 3 entmax epilogue (log-p to O).
// ---------------------------------------------------------------------------
#define SWZB(x) ((x) ^ (((x) >> 3) & 0x70))
#define STGB 16384

__device__ __forceinline__ void cpa16(uint32_t sdst, const void* gsrc) {
    asm volatile("cp.async.cg.shared.global [%0], [%1], 16;" :: "r"(sdst), "l"(gsrc));
}
#define CP_COMMIT asm volatile("cp.async.commit_group;")
#define CP_WAIT1  asm volatile("cp.async.wait_group 1;")

__device__ __forceinline__ void ldsm4(uint32_t* r, uint32_t addr) {
    asm volatile("ldmatrix.sync.aligned.m8n8.x4.shared.b16 {%0,%1,%2,%3}, [%4];"
        : "=r"(r[0]), "=r"(r[1]), "=r"(r[2]), "=r"(r[3]) : "r"(addr));
}

__device__ __forceinline__ void mma_bf16(float* d, const uint32_t* a, const uint32_t* b) {
    asm volatile(
        "mma.sync.aligned.m16n8k16.row.col.f32.bf16.bf16.f32 "
        "{%0,%1,%2,%3}, {%4,%5,%6,%7}, {%8,%9}, {%0,%1,%2,%3};"
        : "+f"(d[0]), "+f"(d[1]), "+f"(d[2]), "+f"(d[3])
        : "r"(a[0]), "r"(a[1]), "r"(a[2]), "r"(a[3]), "r"(b[0]), "r"(b[1]));
}

__global__ __launch_bounds__(256, 2)
void k_gemm(const uint16_t* __restrict__ Ahi, const uint16_t* __restrict__ Alo,
            const uint16_t* __restrict__ Bhi, const uint16_t* __restrict__ Blo,
            const float* __restrict__ bias, const float* __restrict__ res,
            float* __restrict__ O, uint16_t* __restrict__ Ohi, uint16_t* __restrict__ Olo,
            int M, int N, int K, int lda, int ldb, int mode,
            long long aBat, long long bBat, long long oBat,
            float am1f, float halfpow, const float* __restrict__ ib) {
    __shared__ __align__(1024) char sm[3*STGB];
    uint32_t sb32 = (uint32_t)__cvta_generic_to_shared(sm);

    Ahi += (size_t)blockIdx.z * aBat;  Alo += (size_t)blockIdx.z * aBat;
    Bhi += (size_t)blockIdx.z * bBat;  Blo += (size_t)blockIdx.z * bBat;
    if (O)   O   += (size_t)blockIdx.z * oBat;
    if (res) res += (size_t)blockIdx.z * oBat;

    int tid = threadIdx.x;
    int lane = tid & 31, warp = tid >> 5;
    int wm = warp >> 1, wn = warp & 1;           // warp grid 4x2, warp tile 32x64
    int m0 = blockIdx.x * 128, n0 = blockIdx.y * 128;

    // cp.async: 128 rows x 2 chunks per plane; each thread does 4 cpa16
    int grow = tid >> 1, gseg = tid & 1;
    const uint16_t* gAh = Ahi + (size_t)(m0 + grow)*lda + gseg*8;
    const uint16_t* gAl = Alo + (size_t)(m0 + grow)*lda + gseg*8;
    const uint16_t* gBh = Bhi + (size_t)(n0 + grow)*ldb + gseg*8;
    const uint16_t* gBl = Blo + (size_t)(n0 + grow)*ldb + gseg*8;
    uint32_t dS = SWZB(grow*32 + gseg*16);

    // ldmatrix offsets (within stage)
    int mrow = wm*32 + (lane & 15);
    int asg = (lane >> 4) & 1;
    uint32_t oa0 = SWZB(mrow*32 + asg*16);
    uint32_t oa1 = SWZB((mrow+16)*32 + asg*16);
    int nbase = wn*64 + (lane & 7) + ((lane >> 4) << 3);
    int bsg = (lane >> 3) & 1;
    uint32_t ob[4];
#pragma unroll
    for (int g = 0; g < 4; g++)
        ob[g] = 8192 + SWZB((nbase + g*16)*32 + bsg*16);

    float acc[2][8][4];
#pragma unroll
    for (int i = 0; i < 2; i++)
#pragma unroll
        for (int j = 0; j < 8; j++)
#pragma unroll
            for (int v = 0; v < 4; v++) acc[i][j][v] = 0.0f;

    int r = lane >> 2, c = lane & 3;

    auto issue = [&](int tile) {
        uint32_t so = sb32 + (uint32_t)(tile % 3) * STGB;
        cpa16(so + dS,         gAh + tile*16);
        cpa16(so + 4096 + dS,  gAl + tile*16);
        cpa16(so + 8192 + dS,  gBh + tile*16);
        cpa16(so + 12288 + dS, gBl + tile*16);
    };

    auto comp = [&](uint32_t so) {
        uint32_t ah[2][4], al[2][4];
        ldsm4(ah[0], so + oa0);
        ldsm4(ah[1], so + oa1);
        ldsm4(al[0], so + oa0 + 4096);
        ldsm4(al[1], so + oa1 + 4096);
#pragma unroll
        for (int g = 0; g < 4; g++) {
            uint32_t th[4], tl[4];
            ldsm4(th, so + ob[g]);
            ldsm4(tl, so + ob[g] + 4096);
#pragma unroll
            for (int mf = 0; mf < 2; mf++) {
                mma_bf16(acc[mf][2*g],   ah[mf], th);
                mma_bf16(acc[mf][2*g],   ah[mf], tl);
                mma_bf16(acc[mf][2*g],   al[mf], th);
                mma_bf16(acc[mf][2*g+1], ah[mf], th+2);
                mma_bf16(acc[mf][2*g+1], ah[mf], tl+2);
                mma_bf16(acc[mf][2*g+1], al[mf], th+2);
            }
        }
    };

    int nk = K >> 4;
    issue(0); CP_COMMIT;
    if (1 < nk) issue(1);
    CP_COMMIT;
    for (int it = 0; it < nk; ++it) {
        CP_WAIT1;
        __syncthreads();
        int wt = it + 2;
        if (wt < nk) issue(wt);
        CP_COMMIT;
        comp(sb32 + (uint32_t)(it % 3) * STGB);
    }

    float ibv = (mode == 3) ? ib[0] : 0.0f;

    // epilogue: c0:(r, 2c) c1:(r, 2c+1) c2:(r+8, 2c) c3:(r+8, 2c+1)
#pragma unroll
    for (int mf = 0; mf < 2; mf++) {
        int m = m0 + wm*32 + mf*16 + r;
#pragma unroll
        for (int nf = 0; nf < 8; nf++) {
            int n = n0 + wn*64 + nf*8 + c*2;
            float v0 = acc[mf][nf][0], v1 = acc[mf][nf][1];
            float v2 = acc[mf][nf][2], v3 = acc[mf][nf][3];
            if (mode == 2) {
                // fused qkv|qk split
                if (n < 3*CN) {
                    float b0 = bias[n], b1 = bias[n+1];
                    O[(size_t)m*(3*CN) + n]         = v0 + b0;
                    O[(size_t)m*(3*CN) + n + 1]     = v1 + b1;
                    O[(size_t)(m+8)*(3*CN) + n]     = v2 + b0;
                    O[(size_t)(m+8)*(3*CN) + n + 1] = v3 + b1;
                } else {
                    int cc = n - 3*CN;
                    uint32_t hh, ll;
                    pack2(v0, v1, hh, ll);
                    *(uint32_t*)(Ohi + (size_t)m*128 + cc) = hh;
                    *(uint32_t*)(Olo + (size_t)m*128 + cc) = ll;
                    pack2(v2, v3, hh, ll);
                    *(uint32_t*)(Ohi + (size_t)(m+8)*128 + cc) = hh;
                    *(uint32_t*)(Olo + (size_t)(m+8)*128 + cc) = ll;
                }
                continue;
            }
            if (mode == 3) {
                // entmax: O[m][n], m = key index, q = n; gate only q > k
                v0 = entmax_ep(v0, n   > m,   am1f, halfpow, ibv);
                v1 = entmax_ep(v1, n+1 > m,   am1f, halfpow, ibv);
                v2 = entmax_ep(v2, n   > m+8, am1f, halfpow, ibv);
                v3 = entmax_ep(v3, n+1 > m+8, am1f, halfpow, ibv);
            }
            if (bias && mode != 3) {
                float b0 = bias[n], b1 = bias[n+1];
                v0 += b0; v1 += b1; v2 += b0; v3 += b1;
            }
            if (mode == 1) {
                v0 = gelu1(v0); v1 = gelu1(v1); v2 = gelu1(v2); v3 = gelu1(v3);
            }
            if (res) {
                v0 += res[(size_t)m*N + n];
                v1 += res[(size_t)m*N + n + 1];
                v2 += res[(size_t)(m+8)*N + n];
                v3 += res[(size_t)(m+8)*N + n + 1];
            }
            if (Ohi) {
                uint32_t hh, ll;
                pack2(v0, v1, hh, ll);
                *(uint32_t*)(Ohi + (size_t)m*N + n) = hh;
                *(uint32_t*)(Olo + (size_t)m*N + n) = ll;
                pack2(v2, v3, hh, ll);
                *(uint32_t*)(Ohi + (size_t)(m+8)*N + n) = hh;
                *(uint32_t*)(Olo + (size_t)(m+8)*N + n) = ll;
            }
            if (O) {
                O[(size_t)m*N + n]         = v0;
                O[(size_t)m*N + n + 1]     = v1;
                O[(size_t)(m+8)*N + n]     = v2;
                O[(size_t)(m+8)*N + n + 1] = v3;
            }
        }
    }
}

// ---------------------------------------------------------------------------
// mask[b][q][k] += cumsum_{k<q'<=q} logp[b][k][q']   (parallel scan per column)
// ---------------------------------------------------------------------------
__global__ void k_mask(const float* __restrict__ pT, float* __restrict__ mask) {
    int col = blockIdx.x;
    int b = col >> 10, k = col & (TN-1);
    const float* pr = pT + ((size_t)b*TN + k)*TN;
    float* mcol = mask + (size_t)b*TN*TN + k;
    int tid = threadIdx.x;
    int lane = tid & 31, wid = tid >> 5;
    __shared__ float wsum[8];
    __shared__ float s_carry;
    if (tid == 0) s_carry = 0.0f;
    __syncthreads();

    for (int q0 = 0; q0 < TN; q0 += 256) {
        int q = q0 + tid;
        float v = (q > k) ? pr[q] : 0.0f;
#pragma unroll
        for (int o = 1; o < 32; o <<= 1) {
            float nv = __shfl_up_sync(0xFFFFFFFFu, v, o);
            if (lane >= o) v += nv;
        }
        if (lane == 31) wsum[wid] = v;
        __syncthreads();
        if (wid == 0) {
            float w = (lane < 8) ? wsum[lane] : 0.0f;
#pragma unroll
            for (int o = 1; o < 8; o <<= 1) {
                float nw = __shfl_up_sync(0xFFFFFFFFu, w, o);
                if (lane >= o) w += nw;
            }
            if (lane < 8) wsum[lane] = w;
        }
        __syncthreads();
        float incl = s_carry + (wid > 0 ? wsum[wid-1] : 0.0f) + v;
        if (q > k) mcol[(size_t)q*TN] += incl;
        __syncthreads();
        if (tid == 255) s_carry = incl;
        __syncthreads();
    }
}

// ---------------------------------------------------------------------------
// Tiled online-softmax attention. TQ=32 queries/block, 4 q per warp,
// kt loads hoisted across the 4 q (6 LDS feed 8 FMA). Emits bf16 planes.
// ---------------------------------------------------------------------------
#define TQ 32
#define TK 64

__device__ __forceinline__ float wred_max(float v) {
#pragma unroll
    for (int o = 16; o > 0; o >>= 1) v = fmaxf(v, __shfl_xor_sync(0xFFFFFFFFu, v, o));
    return v;
}
__device__ __forceinline__ float wred_sum(float v) {
#pragma unroll
    for (int o = 16; o > 0; o >>= 1) v += __shfl_xor_sync(0xFFFFFFFFu, v, o);
    return v;
}

__global__ __launch_bounds__(256)
void k_attn(const float* __restrict__ qkv, const float* __restrict__ mask,
            uint16_t* __restrict__ yhi, uint16_t* __restrict__ ylo) {
    int q0 = blockIdx.x * TQ, h = blockIdx.y, b = blockIdx.z;
    int tid = threadIdx.x, lane = tid & 31, w = tid >> 5;
    __shared__ float qs[TQ][HDN];
    __shared__ float kt[TK][65];
    __shared__ float vt[TK][HDN];

    const float* base = qkv + (size_t)(b*TN)*3*CN;

    for (int i = tid; i < TQ*16; i += 256) {
        int row = i >> 4, f4 = i & 15;
        float4 v = *(const float4*)(base + (size_t)(q0+row)*3*CN + h*HDN + f4*4);
        *(float4*)&qs[row][f4*4] = v;
    }

    int qa = q0 + w*4;
    const float* mrb = mask + ((size_t)(b*TN) + qa)*TN;
    float mv[4], lv[4];
    float2 av[4];
#pragma unroll
    for (int qq = 0; qq < 4; qq++) {
        mv[qq] = -INFINITY; lv[qq] = 0.0f; av[qq] = make_float2(0.f, 0.f);
    }

    for (int k0 = 0; k0 < q0 + TQ; k0 += TK) {
        __syncthreads();
        {
            int row = tid >> 2;
            const float* kr = base + (size_t)(k0+row)*3*CN + CN + h*HDN;
            const float* vr = kr + CN;
#pragma unroll
            for (int j = 0; j < 4; j++) {
                int f4 = (tid & 3) + 4*j;
                float4 kv = *(const float4*)(kr + f4*4);
                kt[row][f4*4+0] = kv.x; kt[row][f4*4+1] = kv.y;
                kt[row][f4*4+2] = kv.z; kt[row][f4*4+3] = kv.w;
                *(float4*)&vt[row][f4*4] = *(const float4*)(vr + f4*4);
            }
        }
        __syncthreads();

        // dots: kt hoisted across 4 q
        float d1[4], d2[4];
#pragma unroll
        for (int qq = 0; qq < 4; qq++) { d1[qq] = 0.0f; d2[qq] = 0.0f; }
#pragma unroll 16
        for (int dd = 0; dd < HDN; dd++) {
            float k1 = kt[lane][dd];
            float k2 = kt[lane+32][dd];
#pragma unroll
            for (int qq = 0; qq < 4; qq++) {
                float qv = qs[w*4 + qq][dd];
                d1[qq] = fmaf(qv, k1, d1[qq]);
                d2[qq] = fmaf(qv, k2, d2[qq]);
            }
        }

        int k1i = k0 + lane, k2i = k0 + lane + 32;
#pragma unroll
        for (int qq = 0; qq < 4; qq++) {
            int qg = qa + qq;
            const float* mr = mrb + (size_t)qq*TN;
            float s1 = (k1i <= qg) ? fmaf(d1[qq], 0.125f, mr[k1i]) : -INFINITY;
            float s2 = (k2i <= qg) ? fmaf(d2[qq], 0.125f, mr[k2i]) : -INFINITY;

            float tmax = wred_max(fmaxf(s1, s2));
            float mnew = fmaxf(mv[qq], tmax);
            float sc = expf(mv[qq] - mnew);
            float p1 = expf(s1 - mnew);
            float p2 = expf(s2 - mnew);
            float ts = wred_sum(p1 + p2);
            lv[qq] = lv[qq]*sc + ts;
            av[qq].x *= sc; av[qq].y *= sc;
#pragma unroll
            for (int kk = 0; kk < 32; kk++) {
                float pv = __shfl_sync(0xFFFFFFFFu, p1, kk);
                float2 vv = *(const float2*)&vt[kk][lane*2];
                av[qq].x = fmaf(pv, vv.x, av[qq].x);
                av[qq].y = fmaf(pv, vv.y, av[qq].y);
            }
#pragma unroll
            for (int kk = 0; kk < 32; kk++) {
                float pv = __shfl_sync(0xFFFFFFFFu, p2, kk);
                float2 vv = *(const float2*)&vt[kk+32][lane*2];
                av[qq].x = fmaf(pv, vv.x, av[qq].x);
                av[qq].y = fmaf(pv, vv.y, av[qq].y);
            }
            mv[qq] = mnew;
        }
    }

#pragma unroll
    for (int qq = 0; qq < 4; qq++) {
        float inv = 1.0f / lv[qq];
        size_t off = ((size_t)(b*TN) + qa + qq)*CN + h*HDN + lane*2;
        uint32_t hh, ll;
        pack2(av[qq].x*inv, av[qq].y*inv, hh, ll);
        *(uint32_t*)(yhi + off) = hh;
        *(uint32_t*)(ylo + off) = ll;
    }
}

// ---------------------------------------------------------------------------
// Host orchestration
// ---------------------------------------------------------------------------
extern "C" void kernel_launch(void* const* d_in, const int* in_sizes, int n_in,
                              void* d_out, int out_size) {
    const float* wte    = (const float*)d_in[0];
    const float* wpe    = (const float*)d_in[1];
    const float* ln1_w  = (const float*)d_in[2];
    const float* ln1_b  = (const float*)d_in[3];
    const float* attn_w = (const float*)d_in[4];
    const float* attn_b = (const float*)d_in[5];
    const float* qint_w = (const float*)d_in[6];
    const float* kint_w = (const float*)d_in[7];
    const float* int_bias = (const float*)d_in[8];
    const float* proj_w = (const float*)d_in[9];
    const float* proj_b = (const float*)d_in[10];
    const float* ln2_w  = (const float*)d_in[11];
    const float* ln2_b  = (const float*)d_in[12];
    const float* fc_w   = (const float*)d_in[13];
    const float* fc_b   = (const float*)d_in[14];
    const float* fc2_w  = (const float*)d_in[15];
    const float* fc2_b  = (const float*)d_in[16];
    const float* lnf_w  = (const float*)d_in[17];
    const float* lnf_b  = (const float*)d_in[18];
    const int*   idx    = (const int*)d_in[19];
    float* out = (float*)d_out;

    float *px, *pqkv, *pp, *pmask;
    uint16_t *phh, *phl, *pyh, *pyl, *pqh, *pql, *pfh, *pfl;
    uint16_t *wqah, *wqal, *wph, *wpl, *wfh, *wfl, *w2h, *w2l, *wth, *wtl;
    cudaGetSymbolAddress((void**)&px,    g_x);
    cudaGetSymbolAddress((void**)&pqkv,  g_qkv);
    cudaGetSymbolAddress((void**)&pp,    g_p);
    cudaGetSymbolAddress((void**)&pmask, g_mask);
    cudaGetSymbolAddress((void**)&phh,   g_h_hi);  cudaGetSymbolAddress((void**)&phl, g_h_lo);
    cudaGetSymbolAddress((void**)&pyh,   g_y_hi);  cudaGetSymbolAddress((void**)&pyl, g_y_lo);
    cudaGetSymbolAddress((void**)&pqh,   g_qk_hi); cudaGetSymbolAddress((void**)&pql, g_qk_lo);
    cudaGetSymbolAddress((void**)&pfh,   g_fc_hi); cudaGetSymbolAddress((void**)&pfl, g_fc_lo);
    cudaGetSymbolAddress((void**)&wqah,  g_waq_hi); cudaGetSymbolAddress((void**)&wqal, g_waq_lo);
    cudaGetSymbolAddress((void**)&wph,   g_wpj_hi); cudaGetSymbolAddress((void**)&wpl, g_wpj_lo);
    cudaGetSymbolAddress((void**)&wfh,   g_wfc_hi); cudaGetSymbolAddress((void**)&wfl, g_wfc_lo);
    cudaGetSymbolAddress((void**)&w2h,   g_wf2_hi); cudaGetSymbolAddress((void**)&w2l, g_wf2_lo);
    cudaGetSymbolAddress((void**)&wth,   g_wte_hi); cudaGetSymbolAddress((void**)&wtl, g_wte_lo);

    double am1d = 1.000001 - 1.0;
    float am1f = (float)am1d;
    float halfpow = (float)pow(0.5, am1d);

    // weight prep (once per launch)
    k_prep<<<(LN*NAQ*CN/2 + 255)/256, 256>>>(attn_w, qint_w, kint_w, wqah, wqal);
    k_split<<<(LN*CN*CN/4 + 255)/256, 256>>>(proj_w, wph, wpl, LN*CN*CN/4);
    k_split<<<(LN*CFN*CN/4 + 255)/256, 256>>>(fc_w,  wfh, wfl, LN*CFN*CN/4);
    k_split<<<(LN*CN*CFN/4 + 255)/256, 256>>>(fc2_w, w2h, w2l, LN*CN*CFN/4);
    k_split<<<(int)(((size_t)VN*CN/4 + 255)/256), 256>>>(wte, wth, wtl, VN*CN/4);

    k_embed<<<(MN*CN + 255)/256, 256>>>(wte, wpe, idx, px);
    k_zero<<<1024, 256>>>(pmask, BN*TN*TN);

    for (int l = 0; l < LN; ++l) {
        // --- attention sub-block ---
        k_ln<<<MN, 256>>>(px, ln1_w + l*CN, ln1_b + l*CN, phh, phl);
        // fused QKV + qint|kint projection (mode 2)
        k_gemm<<<dim3(MN/128, NAQ/128), 256>>>(phh, phl,
                wqah + (size_t)l*NAQ*CN, wqal + (size_t)l*NAQ*CN,
                attn_b + l*3*CN, nullptr, pqkv, pqh, pql,
                MN, NAQ, CN, CN, CN, 2, 0, 0, 0, 0.f, 0.f, nullptr);
        // rawT[b][k][q] -> log-p directly (entmax in epilogue, mode 3)
        k_gemm<<<dim3(TN/128, TN/128, BN), 256>>>(pqh + 64, pql + 64, pqh, pql,
                nullptr, nullptr, pp, nullptr, nullptr,
                TN, TN, DIN, 128, 128, 3,
                (long long)TN*128, (long long)TN*128, (long long)TN*TN,
                am1f, halfpow, int_bias + l);
        k_mask<<<BN*TN, 256>>>(pp, pmask);
        k_attn<<<dim3(TN/TQ, HN, BN), 256>>>(pqkv, pmask, pyh, pyl);
        k_gemm<<<dim3(MN/128, CN/128), 256>>>(pyh, pyl,
                wph + (size_t)l*CN*CN, wpl + (size_t)l*CN*CN,
                proj_b + l*CN, px, px, nullptr, nullptr,
                MN, CN, CN, CN, CN, 0, 0, 0, 0, 0.f, 0.f, nullptr);
        // --- MLP sub-block (GELU fused into fc epilogue) ---
        k_ln<<<MN, 256>>>(px, ln2_w + l*CN, ln2_b + l*CN, phh, phl);
        k_gemm<<<dim3(MN/128, CFN/128), 256>>>(phh, phl,
                wfh + (size_t)l*CFN*CN, wfl + (size_t)l*CFN*CN,
                fc_b + l*CFN, nullptr, nullptr, pfh, pfl,
                MN, CFN, CN, CN, CN, 1, 0, 0, 0, 0.f, 0.f, nullptr);
        k_gemm<<<dim3(MN/128, CN/128), 256>>>(pfh, pfl,
                w2h + (size_t)l*CN*CFN, w2l + (size_t)l*CN*CFN,
                fc2_b + l*CN, px, px, nullptr, nullptr,
                MN, CN, CFN, CFN, CFN, 0, 0, 0, 0, 0.f, 0.f, nullptr);
    }

    k_ln<<<MN, 256>>>(px, lnf_w, lnf_b, phh, phl);
    k_gemm<<<dim3(MN/128, VN/128), 256>>>(phh, phl, wth, wtl,
            nullptr, nullptr, out, nullptr, nullptr,
            MN, VN, CN, CN, CN, 0, 0, 0, 0, 0.f, 0.f, nullptr);
}

// round 15
// speedup vs baseline: 1.0042x; 1.0042x over previous
#include <cuda_runtime.h>
#include <math.h>
#include <stdint.h>

// ---------------------------------------------------------------------------
// Problem constants
// ---------------------------------------------------------------------------
#define BN 2
#define TN 1024
#define CN 768
#define HN 12
#define HDN 64
#define LN 4
#define DIN 64
#define VN 50304
#define CFN 3072          // 4*C
#define MN (BN*TN)        // 2048 rows
#define NAQ 2432          // 3*C + 128 (fused qkv + qint|kint)

// ---------------------------------------------------------------------------
// Scratch (static device globals; allocation APIs are forbidden)
// ---------------------------------------------------------------------------
__device__ float g_x[MN*CN];
__device__ float g_qkv[MN*3*CN];
__device__ float g_p[BN*TN*TN];     // log-p, layout [b][k][q]
__device__ float g_mask[BN*TN*TN];  // accumulated attn_mask, layout [b][q][k]

// bf16 hi/lo activation planes
__device__ __align__(16) uint16_t g_h_hi[MN*CN],  g_h_lo[MN*CN];
__device__ __align__(16) uint16_t g_y_hi[MN*CN],  g_y_lo[MN*CN];
__device__ __align__(16) uint16_t g_qk_hi[MN*128], g_qk_lo[MN*128];
__device__ __align__(16) uint16_t g_fc_hi[MN*CFN], g_fc_lo[MN*CFN];

// bf16 hi/lo weight planes (split once per launch)
__device__ __align__(16) uint16_t g_waq_hi[LN*NAQ*CN], g_waq_lo[LN*NAQ*CN];
__device__ __align__(16) uint16_t g_wpj_hi[LN*CN*CN],   g_wpj_lo[LN*CN*CN];
__device__ __align__(16) uint16_t g_wfc_hi[LN*CFN*CN],  g_wfc_lo[LN*CFN*CN];
__device__ __align__(16) uint16_t g_wf2_hi[LN*CN*CFN],  g_wf2_lo[LN*CN*CFN];
__device__ __align__(16) uint16_t g_wte_hi[(size_t)VN*CN], g_wte_lo[(size_t)VN*CN];

// ---------------------------------------------------------------------------
// bf16 split helpers
// ---------------------------------------------------------------------------
__device__ __forceinline__ void pack2(float a, float b, uint32_t& h, uint32_t& l) {
    asm("cvt.rn.bf16x2.f32 %0, %1, %2;" : "=r"(h) : "f"(b), "f"(a));
    float ra = a - __uint_as_float(h << 16);
    float rb = b - __uint_as_float(h & 0xFFFF0000u);
    asm("cvt.rn.bf16x2.f32 %0, %1, %2;" : "=r"(l) : "f"(rb), "f"(ra));
}

__device__ __forceinline__ void split1(float v, uint16_t* hp, uint16_t* lp) {
    uint16_t h;
    asm("cvt.rn.bf16.f32 %0, %1;" : "=h"(h) : "f"(v));
    float hf = __uint_as_float(((uint32_t)h) << 16);
    uint16_t l;
    asm("cvt.rn.bf16.f32 %0, %1;" : "=h"(l) : "f"(v - hf));
    *hp = h; *lp = l;
}

// split a f32 tensor into hi/lo bf16 planes (n4 = count/4)
__global__ void k_split(const float* __restrict__ src, uint16_t* __restrict__ hi,
                        uint16_t* __restrict__ lo, int n4) {
    int i = blockIdx.x * blockDim.x + threadIdx.x;
    if (i >= n4) return;
    float4 v = ((const float4*)src)[i];
    uint32_t h0, l0, h1, l1;
    pack2(v.x, v.y, h0, l0);
    pack2(v.z, v.w, h1, l1);
    ((uint2*)hi)[i] = make_uint2(h0, h1);
    ((uint2*)lo)[i] = make_uint2(l0, l1);
}

// build fused [L][2432][CN] weight planes: rows 0..2303 attn_w, 2304..2367
// qint_w, 2368..2431 kint_w
__global__ void k_prep(const float* __restrict__ aw, const float* __restrict__ qw,
                       const float* __restrict__ kw,
                       uint16_t* __restrict__ hi, uint16_t* __restrict__ lo) {
    int i = blockIdx.x * blockDim.x + threadIdx.x;   // pair index
    if (i >= LN*NAQ*CN/2) return;
    int e = i*2;
    int c = e % CN;
    int r = (e / CN) % NAQ;
    int l = e / (NAQ*CN);
    const float* srow;
    if (r < 2304)      srow = aw + ((size_t)l*2304 + r)*CN;
    else if (r < 2368) srow = qw + ((size_t)l*64 + (r-2304))*CN;
    else               srow = kw + ((size_t)l*64 + (r-2368))*CN;
    uint32_t h, lo2;
    pack2(srow[c], srow[c+1], h, lo2);
    *(uint32_t*)(hi + e) = h;
    *(uint32_t*)(lo + e) = lo2;
}

// ---------------------------------------------------------------------------
// Embedding: x = wte[idx] + wpe[:T]
// ---------------------------------------------------------------------------
__global__ void k_embed(const float* __restrict__ wte, const float* __restrict__ wpe,
                        const int* __restrict__ idx, float* __restrict__ x) {
    int i = blockIdx.x * blockDim.x + threadIdx.x;
    if (i >= MN*CN) return;
    int c = i % CN;
    int bt = i / CN;
    int t = bt % TN;
    x[i] = wte[(size_t)idx[bt]*CN + c] + wpe[t*CN + c];
}

__global__ void k_zero(float* __restrict__ p, int n) {
    int i = blockIdx.x * blockDim.x + threadIdx.x;
    for (; i < n; i += gridDim.x * blockDim.x) p[i] = 0.0f;
}

// ---------------------------------------------------------------------------
// LayerNorm (block per row), emits bf16 hi/lo planes
// ---------------------------------------------------------------------------
__global__ void k_ln(const float* __restrict__ x, const float* __restrict__ w,
                     const float* __restrict__ b,
                     uint16_t* __restrict__ ohi, uint16_t* __restrict__ olo) {
    int row = blockIdx.x;
    const float* xr = x + (size_t)row*CN;
    __shared__ float red[256];
    int t = threadIdx.x;
    float lx0 = xr[t], lx1 = xr[t+256], lx2 = xr[t+512];
    red[t] = lx0 + lx1 + lx2;
    __syncthreads();
    for (int st = 128; st > 0; st >>= 1) {
        if (t < st) red[t] += red[t+st];
        __syncthreads();
    }
    float mu = red[0] / (float)CN;
    __syncthreads();
    float d0 = lx0-mu, d1 = lx1-mu, d2 = lx2-mu;
    red[t] = d0*d0 + d1*d1 + d2*d2;
    __syncthreads();
    for (int st = 128; st > 0; st >>= 1) {
        if (t < st) red[t] += red[t+st];
        __syncthreads();
    }
    float var = red[0] / (float)CN;
    float inv = 1.0f / sqrtf(var + 1e-5f);
    size_t base = (size_t)row*CN;
    split1(d0*inv*w[t]     + b[t],     ohi + base + t,     olo + base + t);
    split1(d1*inv*w[t+256] + b[t+256], ohi + base + t+256, olo + base + t+256);
    split1(d2*inv*w[t+512] + b[t+512], ohi + base + t+512, olo + base + t+512);
}

// ---------------------------------------------------------------------------
// GELU helper (tanh approximation, matching reference constants)
// ---------------------------------------------------------------------------
__device__ __forceinline__ float gelu1(float v) {
    float inner = 0.7978845608028654f * (v + 0.044715f*v*v*v);
    return 0.5f*v*(1.0f + tanhf(inner));
}

// ---------------------------------------------------------------------------
// entmax (alpha=1.000001), f32-FAITHFUL bisection — replicates the reference's
// f32 base quantization (clip(Xs-tau) rounded to ulp(1), amplified 1e6x in the
// logit). Freezes when tau_lo + dm == tau_lo (~5 iters). Returns log p.
// ---------------------------------------------------------------------------
__device__ __forceinline__ float lg1e6(float b, float& z) {
    float t = b - 1.0f;
    float u = 1.0e6f * t;
    float e = fmaf(1.0e6f, t, -u);
    float c = fmaf(u*t, fmaf(t, fmaf(-0.25f, t, 0.33333333333333333f), -0.5f), e);
    z = u + c;
    return expf(u) * (1.0f + c*(1.0f + 0.5f*c));
}

__device__ __forceinline__ float entmax_ep(float raw, bool gt, float am1f,
                                           float halfpow, float ib) {
    if (!gt) return 0.0f;
    float r   = raw*0.125f + ib;
    float Xs0 = r * am1f;
    float maxv = fmaxf(Xs0, 0.0f);
    float tau_lo = maxv - 1.0f;
    float tau_hi = maxv - halfpow;
    float dm = tau_hi - tau_lo;
    float zt;
    float f_lo = (lg1e6(fmaxf(Xs0 - tau_lo, 0.0f), zt)
                + lg1e6(fmaxf(-tau_lo, 0.0f), zt)) - 1.0f;
    float z0 = 0.0f, z1 = 0.0f;
#pragma unroll 1
    for (int it = 0; it < 50; ++it) {
        dm *= 0.5f;
        float tm = tau_lo + dm;
        float p0 = lg1e6(fmaxf(Xs0 - tm, 0.0f), z0);
        float p1 = lg1e6(fmaxf(-tm, 0.0f), z1);
        float fm = (p0 + p1) - 1.0f;
        bool take = (fm * f_lo >= 0.0f);
        if (tm == tau_lo) break;
        if (take) tau_lo = tm;
    }
    float d = z1 - z0;
    return (d <= 0.0f) ? -log1pf(expf(d)) : -(d + log1pf(expf(-d)));
}

// ---------------------------------------------------------------------------
// 2xBF16 tensor-core GEMM on pre-split hi/lo planes.
// cp.async 3-stage pipeline, ldmatrix, one barrier per BK=16 tile.
// Block tile 128x128, 8 warps (4Mx2N), warp tile 32x64.
// mode: 0 plain, 1 gelu, 2 fused-qkv split epilogue (n<2304 -> f32 qkv,
//       n>=2304 -> qk planes stride 128), 3 entmax epilogue (log-p to O).
// ---------------------------------------------------------------------------
#define SWZB(x) ((x) ^ (((x) >> 3) & 0x70))
#define STGB 16384

__device__ __forceinline__ void cpa16(uint32_t sdst, const void* gsrc) {
    asm volatile("cp.async.cg.shared.global [%0], [%1], 16;" :: "r"(sdst), "l"(gsrc));
}
#define CP_COMMIT asm volatile("cp.async.commit_group;")
#define CP_WAIT1  asm volatile("cp.async.wait_group 1;")

__device__ __forceinline__ void ldsm4(uint32_t* r, uint32_t addr) {
    asm volatile("ldmatrix.sync.aligned.m8n8.x4.shared.b16 {%0,%1,%2,%3}, [%4];"
        : "=r"(r[0]), "=r"(r[1]), "=r"(r[2]), "=r"(r[3]) : "r"(addr));
}

__device__ __forceinline__ void mma_bf16(float* d, const uint32_t* a, const uint32_t* b) {
    asm volatile(
        "mma.sync.aligned.m16n8k16.row.col.f32.bf16.bf16.f32 "
        "{%0,%1,%2,%3}, {%4,%5,%6,%7}, {%8,%9}, {%0,%1,%2,%3};"
        : "+f"(d[0]), "+f"(d[1]), "+f"(d[2]), "+f"(d[3])
        : "r"(a[0]), "r"(a[1]), "r"(a[2]), "r"(a[3]), "r"(b[0]), "r"(b[1]));
}

__global__ __launch_bounds__(256, 2)
void k_gemm(const uint16_t* __restrict__ Ahi, const uint16_t* __restrict__ Alo,
            const uint16_t* __restrict__ Bhi, const uint16_t* __restrict__ Blo,
            const float* __restrict__ bias, const float* __restrict__ res,
            float* __restrict__ O, uint16_t* __restrict__ Ohi, uint16_t* __restrict__ Olo,
            int M, int N, int K, int lda, int ldb, int mode,
            long long aBat, long long bBat, long long oBat,
            float am1f, float halfpow, const float* __restrict__ ib) {
    __shared__ __align__(1024) char sm[3*STGB];
    uint32_t sb32 = (uint32_t)__cvta_generic_to_shared(sm);

    Ahi += (size_t)blockIdx.z * aBat;  Alo += (size_t)blockIdx.z * aBat;
    Bhi += (size_t)blockIdx.z * bBat;  Blo += (size_t)blockIdx.z * bBat;
    if (O)   O   += (size_t)blockIdx.z * oBat;
    if (res) res += (size_t)blockIdx.z * oBat;

    int tid = threadIdx.x;
    int lane = tid & 31, warp = tid >> 5;
    int wm = warp >> 1, wn = warp & 1;           // warp grid 4x2, warp tile 32x64
    int m0 = blockIdx.x * 128, n0 = blockIdx.y * 128;

    // cp.async: 128 rows x 2 chunks per plane; each thread does 4 cpa16
    int grow = tid >> 1, gseg = tid & 1;
    const uint16_t* gAh = Ahi + (size_t)(m0 + grow)*lda + gseg*8;
    const uint16_t* gAl = Alo + (size_t)(m0 + grow)*lda + gseg*8;
    const uint16_t* gBh = Bhi + (size_t)(n0 + grow)*ldb + gseg*8;
    const uint16_t* gBl = Blo + (size_t)(n0 + grow)*ldb + gseg*8;
    uint32_t dS = SWZB(grow*32 + gseg*16);

    // ldmatrix offsets (within stage)
    int mrow = wm*32 + (lane & 15);
    int asg = (lane >> 4) & 1;
    uint32_t oa0 = SWZB(mrow*32 + asg*16);
    uint32_t oa1 = SWZB((mrow+16)*32 + asg*16);
    int nbase = wn*64 + (lane & 7) + ((lane >> 4) << 3);
    int bsg = (lane >> 3) & 1;
    uint32_t ob[4];
#pragma unroll
    for (int g = 0; g < 4; g++)
        ob[g] = 8192 + SWZB((nbase + g*16)*32 + bsg*16);

    float acc[2][8][4];
#pragma unroll
    for (int i = 0; i < 2; i++)
#pragma unroll
        for (int j = 0; j < 8; j++)
#pragma unroll
            for (int v = 0; v < 4; v++) acc[i][j][v] = 0.0f;

    int r = lane >> 2, c = lane & 3;

    auto issue = [&](int tile) {
        uint32_t so = sb32 + (uint32_t)(tile % 3) * STGB;
        cpa16(so + dS,         gAh + tile*16);
        cpa16(so + 4096 + dS,  gAl + tile*16);
        cpa16(so + 8192 + dS,  gBh + tile*16);
        cpa16(so + 12288 + dS, gBl + tile*16);
    };

    auto comp = [&](uint32_t so) {
        uint32_t ah[2][4], al[2][4];
        ldsm4(ah[0], so + oa0);
        ldsm4(ah[1], so + oa1);
        ldsm4(al[0], so + oa0 + 4096);
        ldsm4(al[1], so + oa1 + 4096);
#pragma unroll
        for (int g = 0; g < 4; g++) {
            uint32_t th[4], tl[4];
            ldsm4(th, so + ob[g]);
            ldsm4(tl, so + ob[g] + 4096);
#pragma unroll
            for (int mf = 0; mf < 2; mf++) {
                mma_bf16(acc[mf][2*g],   ah[mf], th);
                mma_bf16(acc[mf][2*g],   ah[mf], tl);
                mma_bf16(acc[mf][2*g],   al[mf], th);
                mma_bf16(acc[mf][2*g+1], ah[mf], th+2);
                mma_bf16(acc[mf][2*g+1], ah[mf], tl+2);
                mma_bf16(acc[mf][2*g+1], al[mf], th+2);
            }
        }
    };

    int nk = K >> 4;
    issue(0); CP_COMMIT;
    if (1 < nk) issue(1);
    CP_COMMIT;
    for (int it = 0; it < nk; ++it) {
        CP_WAIT1;
        __syncthreads();
        int wt = it + 2;
        if (wt < nk) issue(wt);
        CP_COMMIT;
        comp(sb32 + (uint32_t)(it % 3) * STGB);
    }

    float ibv = (mode == 3) ? ib[0] : 0.0f;

    // epilogue: c0:(r, 2c) c1:(r, 2c+1) c2:(r+8, 2c) c3:(r+8, 2c+1)
#pragma unroll
    for (int mf = 0; mf < 2; mf++) {
        int m = m0 + wm*32 + mf*16 + r;
#pragma unroll
        for (int nf = 0; nf < 8; nf++) {
            int n = n0 + wn*64 + nf*8 + c*2;
            float v0 = acc[mf][nf][0], v1 = acc[mf][nf][1];
            float v2 = acc[mf][nf][2], v3 = acc[mf][nf][3];
            if (mode == 2) {
                // fused qkv|qk split
                if (n < 3*CN) {
                    float b0 = bias[n], b1 = bias[n+1];
                    O[(size_t)m*(3*CN) + n]         = v0 + b0;
                    O[(size_t)m*(3*CN) + n + 1]     = v1 + b1;
                    O[(size_t)(m+8)*(3*CN) + n]     = v2 + b0;
                    O[(size_t)(m+8)*(3*CN) + n + 1] = v3 + b1;
                } else {
                    int cc = n - 3*CN;
                    uint32_t hh, ll;
                    pack2(v0, v1, hh, ll);
                    *(uint32_t*)(Ohi + (size_t)m*128 + cc) = hh;
                    *(uint32_t*)(Olo + (size_t)m*128 + cc) = ll;
                    pack2(v2, v3, hh, ll);
                    *(uint32_t*)(Ohi + (size_t)(m+8)*128 + cc) = hh;
                    *(uint32_t*)(Olo + (size_t)(m+8)*128 + cc) = ll;
                }
                continue;
            }
            if (mode == 3) {
                // entmax: O[m][n], m = key index, q = n; gate only q > k
                v0 = entmax_ep(v0, n   > m,   am1f, halfpow, ibv);
                v1 = entmax_ep(v1, n+1 > m,   am1f, halfpow, ibv);
                v2 = entmax_ep(v2, n   > m+8, am1f, halfpow, ibv);
                v3 = entmax_ep(v3, n+1 > m+8, am1f, halfpow, ibv);
            }
            if (bias && mode != 3) {
                float b0 = bias[n], b1 = bias[n+1];
                v0 += b0; v1 += b1; v2 += b0; v3 += b1;
            }
            if (mode == 1) {
                v0 = gelu1(v0); v1 = gelu1(v1); v2 = gelu1(v2); v3 = gelu1(v3);
            }
            if (res) {
                v0 += res[(size_t)m*N + n];
                v1 += res[(size_t)m*N + n + 1];
                v2 += res[(size_t)(m+8)*N + n];
                v3 += res[(size_t)(m+8)*N + n + 1];
            }
            if (Ohi) {
                uint32_t hh, ll;
                pack2(v0, v1, hh, ll);
                *(uint32_t*)(Ohi + (size_t)m*N + n) = hh;
                *(uint32_t*)(Olo + (size_t)m*N + n) = ll;
                pack2(v2, v3, hh, ll);
                *(uint32_t*)(Ohi + (size_t)(m+8)*N + n) = hh;
                *(uint32_t*)(Olo + (size_t)(m+8)*N + n) = ll;
            }
            if (O) {
                O[(size_t)m*N + n]         = v0;
                O[(size_t)m*N + n + 1]     = v1;
                O[(size_t)(m+8)*N + n]     = v2;
                O[(size_t)(m+8)*N + n + 1] = v3;
            }
        }
    }
}

// ---------------------------------------------------------------------------
// mask[b][q][k] += cumsum_{k<q'<=q} logp[b][k][q']   (parallel scan per column)
// ---------------------------------------------------------------------------
__global__ void k_mask(const float* __restrict__ pT, float* __restrict__ mask) {
    int col = blockIdx.x;
    int b = col >> 10, k = col & (TN-1);
    const float* pr = pT + ((size_t)b*TN + k)*TN;
    float* mcol = mask + (size_t)b*TN*TN + k;
    int tid = threadIdx.x;
    int lane = tid & 31, wid = tid >> 5;
    __shared__ float wsum[8];
    __shared__ float s_carry;
    if (tid == 0) s_carry = 0.0f;
    __syncthreads();

    for (int q0 = 0; q0 < TN; q0 += 256) {
        int q = q0 + tid;
        float v = (q > k) ? pr[q] : 0.0f;
#pragma unroll
        for (int o = 1; o < 32; o <<= 1) {
            float nv = __shfl_up_sync(0xFFFFFFFFu, v, o);
            if (lane >= o) v += nv;
        }
        if (lane == 31) wsum[wid] = v;
        __syncthreads();
        if (wid == 0) {
            float w = (lane < 8) ? wsum[lane] : 0.0f;
#pragma unroll
            for (int o = 1; o < 8; o <<= 1) {
                float nw = __shfl_up_sync(0xFFFFFFFFu, w, o);
                if (lane >= o) w += nw;
            }
            if (lane < 8) wsum[lane] = w;
        }
        __syncthreads();
        float incl = s_carry + (wid > 0 ? wsum[wid-1] : 0.0f) + v;
        if (q > k) mcol[(size_t)q*TN] += incl;
        __syncthreads();
        if (tid == 255) s_carry = incl;
        __syncthreads();
    }
}

// ---------------------------------------------------------------------------
// Tiled online-softmax attention. TQ=32 queries/block, 4 q per warp,
// kt loads hoisted across the 4 q (6 LDS feed 8 FMA). Emits bf16 planes.
// ---------------------------------------------------------------------------
#define TQ 32
#define TK 64

__device__ __forceinline__ float wred_max(float v) {
#pragma unroll
    for (int o = 16; o > 0; o >>= 1) v = fmaxf(v, __shfl_xor_sync(0xFFFFFFFFu, v, o));
    return v;
}
__device__ __forceinline__ float wred_sum(float v) {
#pragma unroll
    for (int o = 16; o > 0; o >>= 1) v += __shfl_xor_sync(0xFFFFFFFFu, v, o);
    return v;
}

__global__ __launch_bounds__(256)
void k_attn(const float* __restrict__ qkv, const float* __restrict__ mask,
            uint16_t* __restrict__ yhi, uint16_t* __restrict__ ylo) {
    int q0 = blockIdx.x * TQ, h = blockIdx.y, b = blockIdx.z;
    int tid = threadIdx.x, lane = tid & 31, w = tid >> 5;
    __shared__ float qs[TQ][HDN];
    __shared__ float kt[TK][65];
    __shared__ float vt[TK][HDN];

    const float* base = qkv + (size_t)(b*TN)*3*CN;

    for (int i = tid; i < TQ*16; i += 256) {
        int row = i >> 4, f4 = i & 15;
        float4 v = *(const float4*)(base + (size_t)(q0+row)*3*CN + h*HDN + f4*4);
        *(float4*)&qs[row][f4*4] = v;
    }

    int qa = q0 + w*4;
    const float* mrb = mask + ((size_t)(b*TN) + qa)*TN;
    float mv[4], lv[4];
    float2 av[4];
#pragma unroll
    for (int qq = 0; qq < 4; qq++) {
        mv[qq] = -INFINITY; lv[qq] = 0.0f; av[qq] = make_float2(0.f, 0.f);
    }

    for (int k0 = 0; k0 < q0 + TQ; k0 += TK) {
        __syncthreads();
        {
            int row = tid >> 2;
            const float* kr = base + (size_t)(k0+row)*3*CN + CN + h*HDN;
            const float* vr = kr + CN;
#pragma unroll
            for (int j = 0; j < 4; j++) {
                int f4 = (tid & 3) + 4*j;
                float4 kv = *(const float4*)(kr + f4*4);
                kt[row][f4*4+0] = kv.x; kt[row][f4*4+1] = kv.y;
                kt[row][f4*4+2] = kv.z; kt[row][f4*4+3] = kv.w;
                *(float4*)&vt[row][f4*4] = *(const float4*)(vr + f4*4);
            }
        }
        __syncthreads();

        // dots: kt hoisted across 4 q
        float d1[4], d2[4];
#pragma unroll
        for (int qq = 0; qq < 4; qq++) { d1[qq] = 0.0f; d2[qq] = 0.0f; }
#pragma unroll 16
        for (int dd = 0; dd < HDN; dd++) {
            float k1 = kt[lane][dd];
            float k2 = kt[lane+32][dd];
#pragma unroll
            for (int qq = 0; qq < 4; qq++) {
                float qv = qs[w*4 + qq][dd];
                d1[qq] = fmaf(qv, k1, d1[qq]);
                d2[qq] = fmaf(qv, k2, d2[qq]);
            }
        }

        int k1i = k0 + lane, k2i = k0 + lane + 32;
#pragma unroll
        for (int qq = 0; qq < 4; qq++) {
            int qg = qa + qq;
            const float* mr = mrb + (size_t)qq*TN;
            float s1 = (k1i <= qg) ? fmaf(d1[qq], 0.125f, mr[k1i]) : -INFINITY;
            float s2 = (k2i <= qg) ? fmaf(d2[qq], 0.125f, mr[k2i]) : -INFINITY;

            float tmax = wred_max(fmaxf(s1, s2));
            float mnew = fmaxf(mv[qq], tmax);
            float sc = expf(mv[qq] - mnew);
            float p1 = expf(s1 - mnew);
            float p2 = expf(s2 - mnew);
            float ts = wred_sum(p1 + p2);
            lv[qq] = lv[qq]*sc + ts;
            av[qq].x *= sc; av[qq].y *= sc;
#pragma unroll
            for (int kk = 0; kk < 32; kk++) {
                float pv = __shfl_sync(0xFFFFFFFFu, p1, kk);
                float2 vv = *(const float2*)&vt[kk][lane*2];
                av[qq].x = fmaf(pv, vv.x, av[qq].x);
                av[qq].y = fmaf(pv, vv.y, av[qq].y);
            }
#pragma unroll
            for (int kk = 0; kk < 32; kk++) {
                float pv = __shfl_sync(0xFFFFFFFFu, p2, kk);
                float2 vv = *(const float2*)&vt[kk+32][lane*2];
                av[qq].x = fmaf(pv, vv.x, av[qq].x);
                av[qq].y = fmaf(pv, vv.y, av[qq].y);
            }
            mv[qq] = mnew;
        }
    }

#pragma unroll
    for (int qq = 0; qq < 4; qq++) {
        float inv = 1.0f / lv[qq];
        size_t off = ((size_t)(b*TN) + qa + qq)*CN + h*HDN + lane*2;
        uint32_t hh, ll;
        pack2(av[qq].x*inv, av[qq].y*inv, hh, ll);
        *(uint32_t*)(yhi + off) = hh;
        *(uint32_t*)(ylo + off) = ll;
    }
}

// ---------------------------------------------------------------------------
// Host orchestration
// ---------------------------------------------------------------------------
extern "C" void kernel_launch(void* const* d_in, const int* in_sizes, int n_in,
                              void* d_out, int out_size) {
    const float* wte    = (const float*)d_in[0];
    const float* wpe    = (const float*)d_in[1];
    const float* ln1_w  = (const float*)d_in[2];
    const float* ln1_b  = (const float*)d_in[3];
    const float* attn_w = (const float*)d_in[4];
    const float* attn_b = (const float*)d_in[5];
    const float* qint_w = (const float*)d_in[6];
    const float* kint_w = (const float*)d_in[7];
    const float* int_bias = (const float*)d_in[8];
    const float* proj_w = (const float*)d_in[9];
    const float* proj_b = (const float*)d_in[10];
    const float* ln2_w  = (const float*)d_in[11];
    const float* ln2_b  = (const float*)d_in[12];
    const float* fc_w   = (const float*)d_in[13];
    const float* fc_b   = (const float*)d_in[14];
    const float* fc2_w  = (const float*)d_in[15];
    const float* fc2_b  = (const float*)d_in[16];
    const float* lnf_w  = (const float*)d_in[17];
    const float* lnf_b  = (const float*)d_in[18];
    const int*   idx    = (const int*)d_in[19];
    float* out = (float*)d_out;

    float *px, *pqkv, *pp, *pmask;
    uint16_t *phh, *phl, *pyh, *pyl, *pqh, *pql, *pfh, *pfl;
    uint16_t *wqah, *wqal, *wph, *wpl, *wfh, *wfl, *w2h, *w2l, *wth, *wtl;
    cudaGetSymbolAddress((void**)&px,    g_x);
    cudaGetSymbolAddress((void**)&pqkv,  g_qkv);
    cudaGetSymbolAddress((void**)&pp,    g_p);
    cudaGetSymbolAddress((void**)&pmask, g_mask);
    cudaGetSymbolAddress((void**)&phh,   g_h_hi);  cudaGetSymbolAddress((void**)&phl, g_h_lo);
    cudaGetSymbolAddress((void**)&pyh,   g_y_hi);  cudaGetSymbolAddress((void**)&pyl, g_y_lo);
    cudaGetSymbolAddress((void**)&pqh,   g_qk_hi); cudaGetSymbolAddress((void**)&pql, g_qk_lo);
    cudaGetSymbolAddress((void**)&pfh,   g_fc_hi); cudaGetSymbolAddress((void**)&pfl, g_fc_lo);
    cudaGetSymbolAddress((void**)&wqah,  g_waq_hi); cudaGetSymbolAddress((void**)&wqal, g_waq_lo);
    cudaGetSymbolAddress((void**)&wph,   g_wpj_hi); cudaGetSymbolAddress((void**)&wpl, g_wpj_lo);
    cudaGetSymbolAddress((void**)&wfh,   g_wfc_hi); cudaGetSymbolAddress((void**)&wfl, g_wfc_lo);
    cudaGetSymbolAddress((void**)&w2h,   g_wf2_hi); cudaGetSymbolAddress((void**)&w2l, g_wf2_lo);
    cudaGetSymbolAddress((void**)&wth,   g_wte_hi); cudaGetSymbolAddress((void**)&wtl, g_wte_lo);

    double am1d = 1.000001 - 1.0;
    float am1f = (float)am1d;
    float halfpow = (float)pow(0.5, am1d);

    // weight prep (once per launch)
    k_prep<<<(LN*NAQ*CN/2 + 255)/256, 256>>>(attn_w, qint_w, kint_w, wqah, wqal);
    k_split<<<(LN*CN*CN/4 + 255)/256, 256>>>(proj_w, wph, wpl, LN*CN*CN/4);
    k_split<<<(LN*CFN*CN/4 + 255)/256, 256>>>(fc_w,  wfh, wfl, LN*CFN*CN/4);
    k_split<<<(LN*CN*CFN/4 + 255)/256, 256>>>(fc2_w, w2h, w2l, LN*CN*CFN/4);
    k_split<<<(int)(((size_t)VN*CN/4 + 255)/256), 256>>>(wte, wth, wtl, VN*CN/4);

    k_embed<<<(MN*CN + 255)/256, 256>>>(wte, wpe, idx, px);
    k_zero<<<1024, 256>>>(pmask, BN*TN*TN);

    for (int l = 0; l < LN; ++l) {
        // --- attention sub-block ---
        k_ln<<<MN, 256>>>(px, ln1_w + l*CN, ln1_b + l*CN, phh, phl);
        // fused QKV + qint|kint projection (mode 2)
        k_gemm<<<dim3(MN/128, NAQ/128), 256>>>(phh, phl,
                wqah + (size_t)l*NAQ*CN, wqal + (size_t)l*NAQ*CN,
                attn_b + l*3*CN, nullptr, pqkv, pqh, pql,
                MN, NAQ, CN, CN, CN, 2, 0, 0, 0, 0.f, 0.f, nullptr);
        // rawT[b][k][q] -> log-p directly (entmax in epilogue, mode 3)
        k_gemm<<<dim3(TN/128, TN/128, BN), 256>>>(pqh + 64, pql + 64, pqh, pql,
                nullptr, nullptr, pp, nullptr, nullptr,
                TN, TN, DIN, 128, 128, 3,
                (long long)TN*128, (long long)TN*128, (long long)TN*TN,
                am1f, halfpow, int_bias + l);
        k_mask<<<BN*TN, 256>>>(pp, pmask);
        k_attn<<<dim3(TN/TQ, HN, BN), 256>>>(pqkv, pmask, pyh, pyl);
        k_gemm<<<dim3(MN/128, CN/128), 256>>>(pyh, pyl,
                wph + (size_t)l*CN*CN, wpl + (size_t)l*CN*CN,
                proj_b + l*CN, px, px, nullptr, nullptr,
                MN, CN, CN, CN, CN, 0, 0, 0, 0, 0.f, 0.f, nullptr);
        // --- MLP sub-block (GELU fused into fc epilogue) ---
        k_ln<<<MN, 256>>>(px, ln2_w + l*CN, ln2_b + l*CN, phh, phl);
        k_gemm<<<dim3(MN/128, CFN/128), 256>>>(phh, phl,
                wfh + (size_t)l*CFN*CN, wfl + (size_t)l*CFN*CN,
                fc_b + l*CFN, nullptr, nullptr, pfh, pfl,
                MN, CFN, CN, CN, CN, 1, 0, 0, 0, 0.f, 0.f, nullptr);
        k_gemm<<<dim3(MN/128, CN/128), 256>>>(pfh, pfl,
                w2h + (size_t)l*CN*CFN, w2l + (size_t)l*CN*CFN,
                fc2_b + l*CN, px, px, nullptr, nullptr,
                MN, CN, CFN, CFN, CFN, 0, 0, 0, 0, 0.f, 0.f, nullptr);
    }

    k_ln<<<MN, 256>>>(px, lnf_w, lnf_b, phh, phl);
    k_gemm<<<dim3(MN/128, VN/128), 256>>>(phh, phl, wth, wtl,
            nullptr, nullptr, out, nullptr, nullptr,
            MN, VN, CN, CN, CN, 0, 0, 0, 0, 0.f, 0.f, nullptr);
}